// round 4
// baseline (speedup 1.0000x reference)
#include <cuda_runtime.h>

// Composed affine map: 9 rows, each padded to 12 floats: [w0..w8, bias, 0, 0]
__device__ float g_aff[9 * 12];

// ---------------------------------------------------------------------------
// Kernel 1: compose the 8 conv layers into one affine map (A, v).
// ---------------------------------------------------------------------------
__global__ void compose_kernel(const float* __restrict__ w,   // [8*9]
                               const float* __restrict__ b) { // [8]
    __shared__ float M[2][9][10];
    int t = threadIdx.x;
    int o = t / 10;
    int c = t % 10;

    if (t < 90) M[0][o][c] = (c < 9 && o == c) ? 1.0f : 0.0f;
    __syncthreads();

    int cur = 0;
    for (int d = 0; d < 8; d++) {
        float acc = 0.0f;
        if (t < 90) {
            int i = o / 3, j = o % 3;
#pragma unroll
            for (int di = -1; di <= 1; di++) {
#pragma unroll
                for (int dj = -1; dj <= 1; dj++) {
                    int ii = i + di, jj = j + dj;
                    if (ii >= 0 && ii < 3 && jj >= 0 && jj < 3) {
                        acc += w[d * 9 + (di + 1) * 3 + (dj + 1)] *
                               M[cur][ii * 3 + jj][c];
                    }
                }
            }
            if (c == 9) acc += b[d];
            M[1 ^ cur][o][c] = acc;
        }
        __syncthreads();
        cur ^= 1;
    }

    if (t < 90) g_aff[o * 12 + c] = M[cur][o][c];
    if (t >= 90 && t < 108) {
        int p = t - 90;
        g_aff[(p / 2) * 12 + 10 + (p % 2)] = 0.0f;
    }
}

// ---------------------------------------------------------------------------
// Kernel 2: vector-staged smem transform, register-trimmed to ~58 live regs
// so 4 blocks/SM (32 warps) keep DRAM in flight.
//   stage-in : coalesced LDG.128 -> STS.128
//   compute  : per thread, its private 144 B chunk (4 rows) in TWO 2-row
//              groups. Each group: 5x LDS.128 window, 9 o-iterations with
//              A row broadcast from smem (reused for both rows), y written
//              back over the chunk (vec + 2 scalars).
//   stage-out: coalesced LDS.128 -> STG.128
// ---------------------------------------------------------------------------
#define TPB 256
#define RPT 4
#define ROWS_PER_BLOCK (TPB * RPT)           // 1024 rows
#define WORDS_PER_BLOCK (ROWS_PER_BLOCK * 9) // 9216 floats = 36864 B

__global__ __launch_bounds__(TPB, 4)
void affine_kernel(const float* __restrict__ x,
                   float* __restrict__ out,
                   int nrows) {
    __shared__ __align__(16) float sA[9 * 12];
    __shared__ __align__(16) float sx[WORDS_PER_BLOCK];

    int t = threadIdx.x;
    long long r0 = (long long)blockIdx.x * ROWS_PER_BLOCK;
    int rows_here = (int)(((long long)nrows - r0) < ROWS_PER_BLOCK
                              ? (nrows - r0) : ROWS_PER_BLOCK);
    int cnt = rows_here * 9;

    if (t < 108) sA[t] = g_aff[t];

    const float* xg = x + r0 * 9;
    float*       og = out + r0 * 9;

    // ---- stage in (fully coalesced) ----
#pragma unroll
    for (int k = 0; k < 9; k++) {
        int fi = (k * TPB + t) * 4;
        if (fi + 4 <= cnt) {
            *(float4*)&sx[fi] = *(const float4*)&xg[fi];
        } else if (fi < cnt) {
            for (int u = fi; u < cnt; u++) sx[u] = xg[u];
        }
    }
    __syncthreads();

    if (rows_here == ROWS_PER_BLOCK) {
        float* chunk = &sx[t * 36];   // this thread's 4 rows (144 B)

        float v[20];
        float y[18];

#pragma unroll
        for (int g = 0; g < 2; g++) {
            // group 0: rows 0,1 in words 0..17  -> window vec0..vec4 (w0..19)
            // group 1: rows 2,3 in words 18..35 -> window vec4..vec8 (w16..35)
            //   (vec4's w16,17 were overwritten by group 0's y — unused here)
#pragma unroll
            for (int k = 0; k < 5; k++)
                *(float4*)&v[4 * k] = *(const float4*)&chunk[16 * g + 4 * k];

            const float* xa = v + (g ? 2 : 0);   // first row of group
            const float* xb = xa + 9;            // second row of group

#pragma unroll
            for (int o = 0; o < 9; o++) {
                float4 a0 = *(const float4*)&sA[o * 12 + 0];
                float4 a1 = *(const float4*)&sA[o * 12 + 4];
                float4 a2 = *(const float4*)&sA[o * 12 + 8]; // x=w8, y=bias

                float acc = fmaf(a0.x, xa[0], a2.y);
                acc = fmaf(a0.y, xa[1], acc);
                acc = fmaf(a0.z, xa[2], acc);
                acc = fmaf(a0.w, xa[3], acc);
                acc = fmaf(a1.x, xa[4], acc);
                acc = fmaf(a1.y, xa[5], acc);
                acc = fmaf(a1.z, xa[6], acc);
                acc = fmaf(a1.w, xa[7], acc);
                y[o] = fmaf(a2.x, xa[8], acc);

                float acd = fmaf(a0.x, xb[0], a2.y);
                acd = fmaf(a0.y, xb[1], acd);
                acd = fmaf(a0.z, xb[2], acd);
                acd = fmaf(a0.w, xb[3], acd);
                acd = fmaf(a1.x, xb[4], acd);
                acd = fmaf(a1.y, xb[5], acd);
                acd = fmaf(a1.z, xb[6], acd);
                acd = fmaf(a1.w, xb[7], acd);
                y[9 + o] = fmaf(a2.x, xb[8], acd);
            }

            if (g == 0) {
                // write words 0..17: 4 vectors + 2 scalars
                *(float4*)&chunk[0]  = *(const float4*)&y[0];
                *(float4*)&chunk[4]  = *(const float4*)&y[4];
                *(float4*)&chunk[8]  = *(const float4*)&y[8];
                *(float4*)&chunk[12] = *(const float4*)&y[12];
                chunk[16] = y[16];
                chunk[17] = y[17];
            } else {
                // write words 18..35: 2 scalars + 4 vectors
                chunk[18] = y[0];
                chunk[19] = y[1];
                *(float4*)&chunk[20] = *(const float4*)&y[2];
                *(float4*)&chunk[24] = *(const float4*)&y[6];
                *(float4*)&chunk[28] = *(const float4*)&y[10];
                *(float4*)&chunk[32] = *(const float4*)&y[14];
            }
        }
    } else {
        // ---- tail block (at most one per grid): scalar per-row ----
        int lr0 = t * RPT;
        for (int lr = lr0; lr < lr0 + RPT && lr < rows_here; lr++) {
            float xp[9];
#pragma unroll
            for (int c = 0; c < 9; c++) xp[c] = sx[lr * 9 + c];
#pragma unroll
            for (int o = 0; o < 9; o++) {
                float acc = sA[o * 12 + 9];
#pragma unroll
                for (int c = 0; c < 9; c++)
                    acc = fmaf(sA[o * 12 + c], xp[c], acc);
                sx[lr * 9 + o] = acc;
            }
        }
    }
    __syncthreads();

    // ---- stage out (fully coalesced) ----
#pragma unroll
    for (int k = 0; k < 9; k++) {
        int fi = (k * TPB + t) * 4;
        if (fi + 4 <= cnt) {
            *(float4*)&og[fi] = *(const float4*)&sx[fi];
        } else if (fi < cnt) {
            for (int u = fi; u < cnt; u++) og[u] = sx[u];
        }
    }
}

extern "C" void kernel_launch(void* const* d_in, const int* in_sizes, int n_in,
                              void* d_out, int out_size) {
    const float* x = (const float*)d_in[0];  // [N*9]
    const float* w = (const float*)d_in[1];  // [8*9]
    const float* b = (const float*)d_in[2];  // [8]
    float* out = (float*)d_out;              // [N*9]

    int nrows = in_sizes[0] / 9;

    compose_kernel<<<1, 96>>>(w, b);

    int blocks = (nrows + ROWS_PER_BLOCK - 1) / ROWS_PER_BLOCK;
    affine_kernel<<<blocks, TPB>>>(x, out, nrows);
}

// round 5
// speedup vs baseline: 1.2220x; 1.2220x over previous
#include <cuda_runtime.h>
#include <cstdint>

// Composed affine map: 9 rows, each padded to 12 floats: [w0..w8, bias, 0, 0]
__device__ float g_aff[9 * 12];

// ---------------------------------------------------------------------------
// Kernel 1: compose the 8 conv layers into one affine map (A, v).
// ---------------------------------------------------------------------------
__global__ void compose_kernel(const float* __restrict__ w,   // [8*9]
                               const float* __restrict__ b) { // [8]
    __shared__ float M[2][9][10];
    int t = threadIdx.x;
    int o = t / 10;
    int c = t % 10;

    if (t < 90) M[0][o][c] = (c < 9 && o == c) ? 1.0f : 0.0f;
    __syncthreads();

    int cur = 0;
    for (int d = 0; d < 8; d++) {
        float acc = 0.0f;
        if (t < 90) {
            int i = o / 3, j = o % 3;
#pragma unroll
            for (int di = -1; di <= 1; di++) {
#pragma unroll
                for (int dj = -1; dj <= 1; dj++) {
                    int ii = i + di, jj = j + dj;
                    if (ii >= 0 && ii < 3 && jj >= 0 && jj < 3) {
                        acc += w[d * 9 + (di + 1) * 3 + (dj + 1)] *
                               M[cur][ii * 3 + jj][c];
                    }
                }
            }
            if (c == 9) acc += b[d];
            M[1 ^ cur][o][c] = acc;
        }
        __syncthreads();
        cur ^= 1;
    }

    if (t < 90) g_aff[o * 12 + c] = M[cur][o][c];
    if (t >= 90 && t < 108) {
        int p = t - 90;
        g_aff[(p / 2) * 12 + 10 + (p % 2)] = 0.0f;
    }
}

// ---------------------------------------------------------------------------
// Kernel 2: TMA-staged affine transform y = A x + v.
//   stage-in : ONE cp.async.bulk global->smem (36864 B) per block; async
//              path, no L1 wavefronts, no staging registers.
//   compute  : thread t owns its 144 B chunk (4 rows) in two 2-row groups;
//              conflict-free LDS.128 windows, A broadcast from smem,
//              y vector-stored back in place.
//   stage-out: ONE cp.async.bulk smem->global (bulk_group) per block.
// 4 blocks/SM overlap the three phases across blocks.
// ---------------------------------------------------------------------------
#define TPB 256
#define RPT 4
#define ROWS_PER_BLOCK (TPB * RPT)            // 1024
#define WORDS_PER_BLOCK (ROWS_PER_BLOCK * 9)  // 9216 floats
#define BYTES_PER_BLOCK (WORDS_PER_BLOCK * 4) // 36864 B

__device__ __forceinline__ uint32_t smem_u32(const void* p) {
    uint32_t a;
    asm("{ .reg .u64 tmp; cvta.to.shared.u64 tmp, %1; cvt.u32.u64 %0, tmp; }"
        : "=r"(a) : "l"(p));
    return a;
}

__global__ __launch_bounds__(TPB, 4)
void affine_kernel(const float* __restrict__ x,
                   float* __restrict__ out,
                   int nrows) {
    __shared__ __align__(16) float sA[9 * 12];
    __shared__ __align__(128) float sx[WORDS_PER_BLOCK];
    __shared__ __align__(8) unsigned long long mbar;

    int t = threadIdx.x;
    long long r0 = (long long)blockIdx.x * ROWS_PER_BLOCK;
    long long rem = (long long)nrows - r0;
    int rows_here = (int)(rem < ROWS_PER_BLOCK ? rem : ROWS_PER_BLOCK);
    bool full = (rows_here == ROWS_PER_BLOCK);
    int cnt = rows_here * 9;

    const float* xg = x + r0 * 9;
    float*       og = out + r0 * 9;

    if (t < 108) sA[t] = g_aff[t];

    uint32_t s_sx = smem_u32(sx);
    uint32_t s_mb = smem_u32(&mbar);

    // ================= stage in =================
    if (full) {
        if (t == 0) {
            asm volatile("mbarrier.init.shared.b64 [%0], %1;"
                         :: "r"(s_mb), "r"(1) : "memory");
        }
        __syncthreads();  // mbar init + sA visible block-wide
        if (t == 0) {
            asm volatile("mbarrier.arrive.expect_tx.shared.b64 _, [%0], %1;"
                         :: "r"(s_mb), "r"((uint32_t)BYTES_PER_BLOCK) : "memory");
            asm volatile(
                "cp.async.bulk.shared::cta.global.mbarrier::complete_tx::bytes "
                "[%0], [%1], %2, [%3];"
                :: "r"(s_sx), "l"(xg), "r"((uint32_t)BYTES_PER_BLOCK), "r"(s_mb)
                : "memory");
        }
        // all threads wait for the tile
        {
            uint32_t done;
            asm volatile(
                "{\n\t.reg .pred p;\n\t"
                "mbarrier.try_wait.parity.acquire.cta.shared::cta.b64 p, [%1], %2;\n\t"
                "selp.b32 %0, 1, 0, p;\n\t}"
                : "=r"(done) : "r"(s_mb), "r"(0u) : "memory");
            if (!done) {
                asm volatile(
                    "{\n\t.reg .pred P1;\n\t"
                    "WAIT_LOOP_%=:\n\t"
                    "mbarrier.try_wait.parity.acquire.cta.shared::cta.b64 P1, [%0], %1, 0x989680;\n\t"
                    "@P1 bra.uni WAIT_DONE_%=;\n\t"
                    "bra.uni WAIT_LOOP_%=;\n\t"
                    "WAIT_DONE_%=:\n\t}"
                    :: "r"(s_mb), "r"(0u) : "memory");
            }
        }
    } else {
        // tail block: coalesced LDG -> STS
#pragma unroll
        for (int k = 0; k < 9; k++) {
            int fi = (k * TPB + t) * 4;
            if (fi + 4 <= cnt) {
                *(float4*)&sx[fi] = *(const float4*)&xg[fi];
            } else if (fi < cnt) {
                for (int u = fi; u < cnt; u++) sx[u] = xg[u];
            }
        }
        __syncthreads();
    }

    // ================= compute =================
    if (full) {
        float* chunk = &sx[t * 36];   // this thread's 4 rows (144 B)
        float v[20];
        float y[18];

#pragma unroll
        for (int g = 0; g < 2; g++) {
            // group 0: rows 0,1 (words 0..17),  window = words 0..19
            // group 1: rows 2,3 (words 18..35), window = words 16..35
#pragma unroll
            for (int k = 0; k < 5; k++)
                *(float4*)&v[4 * k] = *(const float4*)&chunk[16 * g + 4 * k];

            const float* xa = v + (g ? 2 : 0);
            const float* xb = xa + 9;

#pragma unroll
            for (int o = 0; o < 9; o++) {
                float4 a0 = *(const float4*)&sA[o * 12 + 0];
                float4 a1 = *(const float4*)&sA[o * 12 + 4];
                float4 a2 = *(const float4*)&sA[o * 12 + 8]; // x=w8, y=bias

                float acc = fmaf(a0.x, xa[0], a2.y);
                acc = fmaf(a0.y, xa[1], acc);
                acc = fmaf(a0.z, xa[2], acc);
                acc = fmaf(a0.w, xa[3], acc);
                acc = fmaf(a1.x, xa[4], acc);
                acc = fmaf(a1.y, xa[5], acc);
                acc = fmaf(a1.z, xa[6], acc);
                acc = fmaf(a1.w, xa[7], acc);
                y[o] = fmaf(a2.x, xa[8], acc);

                float acd = fmaf(a0.x, xb[0], a2.y);
                acd = fmaf(a0.y, xb[1], acd);
                acd = fmaf(a0.z, xb[2], acd);
                acd = fmaf(a0.w, xb[3], acd);
                acd = fmaf(a1.x, xb[4], acd);
                acd = fmaf(a1.y, xb[5], acd);
                acd = fmaf(a1.z, xb[6], acd);
                acd = fmaf(a1.w, xb[7], acd);
                y[9 + o] = fmaf(a2.x, xb[8], acd);
            }

            if (g == 0) {
                *(float4*)&chunk[0]  = *(const float4*)&y[0];
                *(float4*)&chunk[4]  = *(const float4*)&y[4];
                *(float4*)&chunk[8]  = *(const float4*)&y[8];
                *(float4*)&chunk[12] = *(const float4*)&y[12];
                *(float2*)&chunk[16] = *(const float2*)&y[16];
            } else {
                *(float2*)&chunk[18] = *(const float2*)&y[0];
                *(float4*)&chunk[20] = *(const float4*)&y[2];
                *(float4*)&chunk[24] = *(const float4*)&y[6];
                *(float4*)&chunk[28] = *(const float4*)&y[10];
                *(float4*)&chunk[32] = *(const float4*)&y[14];
            }
        }
    } else {
        int lr0 = t * RPT;
        for (int lr = lr0; lr < lr0 + RPT && lr < rows_here; lr++) {
            float xp[9];
#pragma unroll
            for (int c = 0; c < 9; c++) xp[c] = sx[lr * 9 + c];
#pragma unroll
            for (int o = 0; o < 9; o++) {
                float acc = sA[o * 12 + 9];
#pragma unroll
                for (int c = 0; c < 9; c++)
                    acc = fmaf(sA[o * 12 + c], xp[c], acc);
                sx[lr * 9 + o] = acc;
            }
        }
    }
    __syncthreads();

    // ================= stage out =================
    if (full) {
        if (t == 0) {
            asm volatile("fence.proxy.async.shared::cta;" ::: "memory");
            asm volatile(
                "cp.async.bulk.global.shared::cta.bulk_group [%0], [%1], %2;"
                :: "l"(og), "r"(s_sx), "r"((uint32_t)BYTES_PER_BLOCK)
                : "memory");
            asm volatile("cp.async.bulk.commit_group;" ::: "memory");
            asm volatile("cp.async.bulk.wait_group 0;" ::: "memory");
        }
    } else {
#pragma unroll
        for (int k = 0; k < 9; k++) {
            int fi = (k * TPB + t) * 4;
            if (fi + 4 <= cnt) {
                *(float4*)&og[fi] = *(const float4*)&sx[fi];
            } else if (fi < cnt) {
                for (int u = fi; u < cnt; u++) og[u] = sx[u];
            }
        }
    }
}

extern "C" void kernel_launch(void* const* d_in, const int* in_sizes, int n_in,
                              void* d_out, int out_size) {
    const float* x = (const float*)d_in[0];  // [N*9]
    const float* w = (const float*)d_in[1];  // [8*9]
    const float* b = (const float*)d_in[2];  // [8]
    float* out = (float*)d_out;              // [N*9]

    int nrows = in_sizes[0] / 9;

    compose_kernel<<<1, 96>>>(w, b);

    int blocks = (nrows + ROWS_PER_BLOCK - 1) / ROWS_PER_BLOCK;
    affine_kernel<<<blocks, TPB>>>(x, out, nrows);
}

// round 6
// speedup vs baseline: 1.5977x; 1.3074x over previous
#include <cuda_runtime.h>
#include <cstdint>

// Composed affine map: 9 rows, each padded to 12 floats: [w0..w8, bias, 0, 0]
__device__ float g_aff[9 * 12];

// ---------------------------------------------------------------------------
// Kernel 1: compose the 8 conv layers into one affine map (A, v).
// ---------------------------------------------------------------------------
__global__ void compose_kernel(const float* __restrict__ w,   // [8*9]
                               const float* __restrict__ b) { // [8]
    __shared__ float M[2][9][10];
    int t = threadIdx.x;
    int o = t / 10;
    int c = t % 10;

    if (t < 90) M[0][o][c] = (c < 9 && o == c) ? 1.0f : 0.0f;
    __syncthreads();

    int cur = 0;
    for (int d = 0; d < 8; d++) {
        float acc = 0.0f;
        if (t < 90) {
            int i = o / 3, j = o % 3;
#pragma unroll
            for (int di = -1; di <= 1; di++) {
#pragma unroll
                for (int dj = -1; dj <= 1; dj++) {
                    int ii = i + di, jj = j + dj;
                    if (ii >= 0 && ii < 3 && jj >= 0 && jj < 3) {
                        acc += w[d * 9 + (di + 1) * 3 + (dj + 1)] *
                               M[cur][ii * 3 + jj][c];
                    }
                }
            }
            if (c == 9) acc += b[d];
            M[1 ^ cur][o][c] = acc;
        }
        __syncthreads();
        cur ^= 1;
    }

    if (t < 90) g_aff[o * 12 + c] = M[cur][o][c];
    if (t >= 90 && t < 108) {
        int p = t - 90;
        g_aff[(p / 2) * 12 + 10 + (p % 2)] = 0.0f;
    }
}

// ---------------------------------------------------------------------------
// Kernel 2: persistent double-buffered TMA pipeline.
//   per CTA: loop over tiles (stride gridDim); for each tile:
//     - prefetch tile+grid into other buffer (wait_group 0 -> expect_tx -> bulk ld)
//     - mbarrier wait for this tile
//     - compute in place (vector LDS/STS, conflict-free 144 B chunks)
//     - __syncthreads, fence.proxy.async, async bulk store (commit, no wait)
// ---------------------------------------------------------------------------
#define TPB 128
#define RPT 4
#define ROWS_PER_TILE (TPB * RPT)            // 512
#define WORDS_PER_TILE (ROWS_PER_TILE * 9)   // 4608
#define BYTES_PER_TILE (WORDS_PER_TILE * 4)  // 18432

__device__ __forceinline__ uint32_t smem_u32(const void* p) {
    uint32_t a;
    asm("{ .reg .u64 tmp; cvta.to.shared.u64 tmp, %1; cvt.u32.u64 %0, tmp; }"
        : "=r"(a) : "l"(p));
    return a;
}

__device__ __forceinline__ void mbar_wait(uint32_t mb, uint32_t parity) {
    uint32_t done;
    asm volatile(
        "{\n\t.reg .pred p;\n\t"
        "mbarrier.try_wait.parity.acquire.cta.shared::cta.b64 p, [%1], %2;\n\t"
        "selp.b32 %0, 1, 0, p;\n\t}"
        : "=r"(done) : "r"(mb), "r"(parity) : "memory");
    if (!done) {
        asm volatile(
            "{\n\t.reg .pred P1;\n\t"
            "WAIT_LOOP_%=:\n\t"
            "mbarrier.try_wait.parity.acquire.cta.shared::cta.b64 P1, [%0], %1, 0x989680;\n\t"
            "@P1 bra.uni WAIT_DONE_%=;\n\t"
            "bra.uni WAIT_LOOP_%=;\n\t"
            "WAIT_DONE_%=:\n\t}"
            :: "r"(mb), "r"(parity) : "memory");
    }
}

__global__ __launch_bounds__(TPB, 6)
void affine_kernel(const float* __restrict__ x,
                   float* __restrict__ out,
                   int nrows) {
    __shared__ __align__(128) float sx[2][WORDS_PER_TILE];
    __shared__ __align__(16) float sA[9 * 12];
    __shared__ __align__(8) unsigned long long mbar[2];

    int t = threadIdx.x;
    int ntiles = (nrows + ROWS_PER_TILE - 1) / ROWS_PER_TILE;

    if (t < 108) sA[t] = g_aff[t];
    if (t == 0) {
        asm volatile("mbarrier.init.shared.b64 [%0], %1;"
                     :: "r"(smem_u32(&mbar[0])), "r"(1) : "memory");
        asm volatile("mbarrier.init.shared.b64 [%0], %1;"
                     :: "r"(smem_u32(&mbar[1])), "r"(1) : "memory");
    }
    __syncthreads();

    uint32_t s_mb0 = smem_u32(&mbar[0]);
    uint32_t s_mb1 = smem_u32(&mbar[1]);
    uint32_t s_b0  = smem_u32(sx[0]);
    uint32_t s_b1  = smem_u32(sx[1]);

    uint32_t ph[2] = {0u, 0u};

    // ---- prologue: prefetch my first tile (if full) into buffer 0 ----
    {
        long long tile0 = blockIdx.x;
        if (tile0 < ntiles && t == 0) {
            long long rows0 = (long long)nrows - tile0 * ROWS_PER_TILE;
            if (rows0 >= ROWS_PER_TILE) {
                const float* xg = x + tile0 * (long long)ROWS_PER_TILE * 9;
                asm volatile("mbarrier.arrive.expect_tx.shared.b64 _, [%0], %1;"
                             :: "r"(s_mb0), "r"((uint32_t)BYTES_PER_TILE) : "memory");
                asm volatile(
                    "cp.async.bulk.shared::cta.global.mbarrier::complete_tx::bytes "
                    "[%0], [%1], %2, [%3];"
                    :: "r"(s_b0), "l"(xg), "r"((uint32_t)BYTES_PER_TILE), "r"(s_mb0)
                    : "memory");
            }
        }
    }

    int li = 0;
    for (long long tile = blockIdx.x; tile < ntiles; tile += gridDim.x, li++) {
        int b = li & 1;
        uint32_t s_mb_cur = b ? s_mb1 : s_mb0;
        uint32_t s_mb_nxt = b ? s_mb0 : s_mb1;
        uint32_t s_b_nxt  = b ? s_b0 : s_b1;
        float* buf = sx[b];

        long long r0 = tile * ROWS_PER_TILE;
        int rows_here = (int)((((long long)nrows - r0) < ROWS_PER_TILE)
                                  ? (nrows - r0) : ROWS_PER_TILE);
        bool full = (rows_here == ROWS_PER_TILE);
        int cnt = rows_here * 9;
        const float* xg = x + r0 * 9;
        float*       og = out + r0 * 9;

        // ---- prefetch next tile into the other buffer ----
        long long ntile = tile + gridDim.x;
        if (ntile < ntiles && t == 0) {
            long long nrows_next = (long long)nrows - ntile * ROWS_PER_TILE;
            if (nrows_next >= ROWS_PER_TILE) {
                // buffer reuse: the store issued from that buffer 1 iter ago
                // must have finished reading smem
                asm volatile("cp.async.bulk.wait_group 0;" ::: "memory");
                const float* xgn = x + ntile * (long long)ROWS_PER_TILE * 9;
                asm volatile("mbarrier.arrive.expect_tx.shared.b64 _, [%0], %1;"
                             :: "r"(s_mb_nxt), "r"((uint32_t)BYTES_PER_TILE) : "memory");
                asm volatile(
                    "cp.async.bulk.shared::cta.global.mbarrier::complete_tx::bytes "
                    "[%0], [%1], %2, [%3];"
                    :: "r"(s_b_nxt), "l"(xgn), "r"((uint32_t)BYTES_PER_TILE), "r"(s_mb_nxt)
                    : "memory");
            }
        }

        if (full) {
            // ---- consume TMA-loaded tile ----
            mbar_wait(s_mb_cur, ph[b]);
            ph[b] ^= 1;

            float* chunk = &buf[t * 36];
            float v[20];
            float y[18];

#pragma unroll
            for (int g = 0; g < 2; g++) {
#pragma unroll
                for (int k = 0; k < 5; k++)
                    *(float4*)&v[4 * k] = *(const float4*)&chunk[16 * g + 4 * k];

                const float* xa = v + (g ? 2 : 0);
                const float* xb = xa + 9;

#pragma unroll
                for (int o = 0; o < 9; o++) {
                    float4 a0 = *(const float4*)&sA[o * 12 + 0];
                    float4 a1 = *(const float4*)&sA[o * 12 + 4];
                    float4 a2 = *(const float4*)&sA[o * 12 + 8]; // x=w8, y=bias

                    float acc = fmaf(a0.x, xa[0], a2.y);
                    acc = fmaf(a0.y, xa[1], acc);
                    acc = fmaf(a0.z, xa[2], acc);
                    acc = fmaf(a0.w, xa[3], acc);
                    acc = fmaf(a1.x, xa[4], acc);
                    acc = fmaf(a1.y, xa[5], acc);
                    acc = fmaf(a1.z, xa[6], acc);
                    acc = fmaf(a1.w, xa[7], acc);
                    y[o] = fmaf(a2.x, xa[8], acc);

                    float acd = fmaf(a0.x, xb[0], a2.y);
                    acd = fmaf(a0.y, xb[1], acd);
                    acd = fmaf(a0.z, xb[2], acd);
                    acd = fmaf(a0.w, xb[3], acd);
                    acd = fmaf(a1.x, xb[4], acd);
                    acd = fmaf(a1.y, xb[5], acd);
                    acd = fmaf(a1.z, xb[6], acd);
                    acd = fmaf(a1.w, xb[7], acd);
                    y[9 + o] = fmaf(a2.x, xb[8], acd);
                }

                if (g == 0) {
                    *(float4*)&chunk[0]  = *(const float4*)&y[0];
                    *(float4*)&chunk[4]  = *(const float4*)&y[4];
                    *(float4*)&chunk[8]  = *(const float4*)&y[8];
                    *(float4*)&chunk[12] = *(const float4*)&y[12];
                    *(float2*)&chunk[16] = *(const float2*)&y[16];
                } else {
                    *(float2*)&chunk[18] = *(const float2*)&y[0];
                    *(float4*)&chunk[20] = *(const float4*)&y[2];
                    *(float4*)&chunk[24] = *(const float4*)&y[6];
                    *(float4*)&chunk[28] = *(const float4*)&y[10];
                    *(float4*)&chunk[32] = *(const float4*)&y[14];
                }
            }

            __syncthreads();  // all y written before async store reads smem
            if (t == 0) {
                asm volatile("fence.proxy.async.shared::cta;" ::: "memory");
                asm volatile(
                    "cp.async.bulk.global.shared::cta.bulk_group [%0], [%1], %2;"
                    :: "l"(og), "r"(smem_u32(buf)), "r"((uint32_t)BYTES_PER_TILE)
                    : "memory");
                asm volatile("cp.async.bulk.commit_group;" ::: "memory");
            }
            // no wait: store drains while we move on
        } else {
            // ---- partial tile (global last tile only): synchronous path ----
            if (t == 0) {
                // make sure any pending store from this buffer finished
                asm volatile("cp.async.bulk.wait_group 0;" ::: "memory");
            }
            __syncthreads();
#pragma unroll
            for (int k = 0; k < (WORDS_PER_TILE / (TPB * 4)); k++) {
                int fi = (k * TPB + t) * 4;
                if (fi + 4 <= cnt) {
                    *(float4*)&buf[fi] = *(const float4*)&xg[fi];
                } else if (fi < cnt) {
                    for (int u = fi; u < cnt; u++) buf[u] = xg[u];
                }
            }
            __syncthreads();
            int lr0 = t * RPT;
            for (int lr = lr0; lr < lr0 + RPT && lr < rows_here; lr++) {
                float xp[9];
#pragma unroll
                for (int c = 0; c < 9; c++) xp[c] = buf[lr * 9 + c];
#pragma unroll
                for (int o = 0; o < 9; o++) {
                    float acc = sA[o * 12 + 9];
#pragma unroll
                    for (int c = 0; c < 9; c++)
                        acc = fmaf(sA[o * 12 + c], xp[c], acc);
                    buf[lr * 9 + o] = acc;
                }
            }
            __syncthreads();
#pragma unroll
            for (int k = 0; k < (WORDS_PER_TILE / (TPB * 4)); k++) {
                int fi = (k * TPB + t) * 4;
                if (fi + 4 <= cnt) {
                    *(float4*)&og[fi] = *(const float4*)&buf[fi];
                } else if (fi < cnt) {
                    for (int u = fi; u < cnt; u++) og[u] = buf[u];
                }
            }
        }
    }

    // drain the last async store before exit
    if (t == 0) {
        asm volatile("cp.async.bulk.wait_group 0;" ::: "memory");
    }
}

extern "C" void kernel_launch(void* const* d_in, const int* in_sizes, int n_in,
                              void* d_out, int out_size) {
    const float* x = (const float*)d_in[0];  // [N*9]
    const float* w = (const float*)d_in[1];  // [8*9]
    const float* b = (const float*)d_in[2];  // [8]
    float* out = (float*)d_out;              // [N*9]

    int nrows = in_sizes[0] / 9;

    compose_kernel<<<1, 96>>>(w, b);

    int ntiles = (nrows + ROWS_PER_TILE - 1) / ROWS_PER_TILE;
    int blocks = 148 * 6;
    if (blocks > ntiles) blocks = ntiles;
    affine_kernel<<<blocks, TPB>>>(x, out, nrows);
}

// round 7
// speedup vs baseline: 2.1989x; 1.3763x over previous
#include <cuda_runtime.h>
#include <cstdint>

// Composed affine map: 9 rows, each padded to 12 floats: [w0..w8, bias, 0, 0]
__device__ float g_aff[9 * 12];
__constant__ float c_aff[9 * 12];

// ---------------------------------------------------------------------------
// Kernel 1: compose the 8 conv layers into one affine map (A, v).
// ---------------------------------------------------------------------------
__global__ void compose_kernel(const float* __restrict__ w,   // [8*9]
                               const float* __restrict__ b) { // [8]
    __shared__ float M[2][9][10];
    int t = threadIdx.x;
    int o = t / 10;
    int c = t % 10;

    if (t < 90) M[0][o][c] = (c < 9 && o == c) ? 1.0f : 0.0f;
    __syncthreads();

    int cur = 0;
    for (int d = 0; d < 8; d++) {
        float acc = 0.0f;
        if (t < 90) {
            int i = o / 3, j = o % 3;
#pragma unroll
            for (int di = -1; di <= 1; di++) {
#pragma unroll
                for (int dj = -1; dj <= 1; dj++) {
                    int ii = i + di, jj = j + dj;
                    if (ii >= 0 && ii < 3 && jj >= 0 && jj < 3) {
                        acc += w[d * 9 + (di + 1) * 3 + (dj + 1)] *
                               M[cur][ii * 3 + jj][c];
                    }
                }
            }
            if (c == 9) acc += b[d];
            M[1 ^ cur][o][c] = acc;
        }
        __syncthreads();
        cur ^= 1;
    }

    if (t < 90) g_aff[o * 12 + c] = M[cur][o][c];
    if (t >= 90 && t < 108) {
        int p = t - 90;
        g_aff[(p / 2) * 12 + 10 + (p % 2)] = 0.0f;
    }
}

// ---------------------------------------------------------------------------
// Kernel 2: persistent double-buffered TMA pipeline.
//   - A in __constant__ (separate const port; no L1 traffic for broadcasts)
//   - buffer reuse gated by cp.async.bulk.wait_group.READ (smem reads done),
//     not full store completion
// ---------------------------------------------------------------------------
#define TPB 128
#define RPT 4
#define ROWS_PER_TILE (TPB * RPT)            // 512
#define WORDS_PER_TILE (ROWS_PER_TILE * 9)   // 4608
#define BYTES_PER_TILE (WORDS_PER_TILE * 4)  // 18432

__device__ __forceinline__ uint32_t smem_u32(const void* p) {
    uint32_t a;
    asm("{ .reg .u64 tmp; cvta.to.shared.u64 tmp, %1; cvt.u32.u64 %0, tmp; }"
        : "=r"(a) : "l"(p));
    return a;
}

__device__ __forceinline__ void mbar_wait(uint32_t mb, uint32_t parity) {
    uint32_t done;
    asm volatile(
        "{\n\t.reg .pred p;\n\t"
        "mbarrier.try_wait.parity.acquire.cta.shared::cta.b64 p, [%1], %2;\n\t"
        "selp.b32 %0, 1, 0, p;\n\t}"
        : "=r"(done) : "r"(mb), "r"(parity) : "memory");
    if (!done) {
        asm volatile(
            "{\n\t.reg .pred P1;\n\t"
            "WAIT_LOOP_%=:\n\t"
            "mbarrier.try_wait.parity.acquire.cta.shared::cta.b64 P1, [%0], %1, 0x989680;\n\t"
            "@P1 bra.uni WAIT_DONE_%=;\n\t"
            "bra.uni WAIT_LOOP_%=;\n\t"
            "WAIT_DONE_%=:\n\t}"
            :: "r"(mb), "r"(parity) : "memory");
    }
}

__global__ __launch_bounds__(TPB, 6)
void affine_kernel(const float* __restrict__ x,
                   float* __restrict__ out,
                   int nrows) {
    __shared__ __align__(128) float sx[2][WORDS_PER_TILE];
    __shared__ __align__(8) unsigned long long mbar[2];

    int t = threadIdx.x;
    int ntiles = (nrows + ROWS_PER_TILE - 1) / ROWS_PER_TILE;

    if (t == 0) {
        asm volatile("mbarrier.init.shared.b64 [%0], %1;"
                     :: "r"(smem_u32(&mbar[0])), "r"(1) : "memory");
        asm volatile("mbarrier.init.shared.b64 [%0], %1;"
                     :: "r"(smem_u32(&mbar[1])), "r"(1) : "memory");
    }
    __syncthreads();

    uint32_t s_mb0 = smem_u32(&mbar[0]);
    uint32_t s_mb1 = smem_u32(&mbar[1]);
    uint32_t s_b0  = smem_u32(sx[0]);
    uint32_t s_b1  = smem_u32(sx[1]);

    uint32_t ph[2] = {0u, 0u};

    // ---- prologue: prefetch my first tile (if full) into buffer 0 ----
    {
        long long tile0 = blockIdx.x;
        if (tile0 < ntiles && t == 0) {
            long long rows0 = (long long)nrows - tile0 * ROWS_PER_TILE;
            if (rows0 >= ROWS_PER_TILE) {
                const float* xg = x + tile0 * (long long)ROWS_PER_TILE * 9;
                asm volatile("mbarrier.arrive.expect_tx.shared.b64 _, [%0], %1;"
                             :: "r"(s_mb0), "r"((uint32_t)BYTES_PER_TILE) : "memory");
                asm volatile(
                    "cp.async.bulk.shared::cta.global.mbarrier::complete_tx::bytes "
                    "[%0], [%1], %2, [%3];"
                    :: "r"(s_b0), "l"(xg), "r"((uint32_t)BYTES_PER_TILE), "r"(s_mb0)
                    : "memory");
            }
        }
    }

    int li = 0;
    for (long long tile = blockIdx.x; tile < ntiles; tile += gridDim.x, li++) {
        int b = li & 1;
        uint32_t s_mb_cur = b ? s_mb1 : s_mb0;
        uint32_t s_mb_nxt = b ? s_mb0 : s_mb1;
        uint32_t s_b_nxt  = b ? s_b0 : s_b1;
        float* buf = sx[b];

        long long r0 = tile * ROWS_PER_TILE;
        int rows_here = (int)((((long long)nrows - r0) < ROWS_PER_TILE)
                                  ? (nrows - r0) : ROWS_PER_TILE);
        bool full = (rows_here == ROWS_PER_TILE);
        int cnt = rows_here * 9;
        const float* xg = x + r0 * 9;
        float*       og = out + r0 * 9;

        // ---- prefetch next tile into the other buffer ----
        long long ntile = tile + gridDim.x;
        if (ntile < ntiles && t == 0) {
            long long nrows_next = (long long)nrows - ntile * ROWS_PER_TILE;
            if (nrows_next >= ROWS_PER_TILE) {
                // only need the prior store's SMEM READS done to reuse buffer
                asm volatile("cp.async.bulk.wait_group.read 0;" ::: "memory");
                const float* xgn = x + ntile * (long long)ROWS_PER_TILE * 9;
                asm volatile("mbarrier.arrive.expect_tx.shared.b64 _, [%0], %1;"
                             :: "r"(s_mb_nxt), "r"((uint32_t)BYTES_PER_TILE) : "memory");
                asm volatile(
                    "cp.async.bulk.shared::cta.global.mbarrier::complete_tx::bytes "
                    "[%0], [%1], %2, [%3];"
                    :: "r"(s_b_nxt), "l"(xgn), "r"((uint32_t)BYTES_PER_TILE), "r"(s_mb_nxt)
                    : "memory");
            }
        }

        if (full) {
            // ---- consume TMA-loaded tile ----
            mbar_wait(s_mb_cur, ph[b]);
            ph[b] ^= 1;

            float* chunk = &buf[t * 36];
            float v[20];
            float y[18];

#pragma unroll
            for (int g = 0; g < 2; g++) {
#pragma unroll
                for (int k = 0; k < 5; k++)
                    *(float4*)&v[4 * k] = *(const float4*)&chunk[16 * g + 4 * k];

                const float* xa = v + (g ? 2 : 0);
                const float* xb = xa + 9;

#pragma unroll
                for (int o = 0; o < 9; o++) {
                    float4 a0 = *(const float4*)&c_aff[o * 12 + 0];
                    float4 a1 = *(const float4*)&c_aff[o * 12 + 4];
                    float4 a2 = *(const float4*)&c_aff[o * 12 + 8]; // x=w8, y=bias

                    float acc = fmaf(a0.x, xa[0], a2.y);
                    acc = fmaf(a0.y, xa[1], acc);
                    acc = fmaf(a0.z, xa[2], acc);
                    acc = fmaf(a0.w, xa[3], acc);
                    acc = fmaf(a1.x, xa[4], acc);
                    acc = fmaf(a1.y, xa[5], acc);
                    acc = fmaf(a1.z, xa[6], acc);
                    acc = fmaf(a1.w, xa[7], acc);
                    y[o] = fmaf(a2.x, xa[8], acc);

                    float acd = fmaf(a0.x, xb[0], a2.y);
                    acd = fmaf(a0.y, xb[1], acd);
                    acd = fmaf(a0.z, xb[2], acd);
                    acd = fmaf(a0.w, xb[3], acd);
                    acd = fmaf(a1.x, xb[4], acd);
                    acd = fmaf(a1.y, xb[5], acd);
                    acd = fmaf(a1.z, xb[6], acd);
                    acd = fmaf(a1.w, xb[7], acd);
                    y[9 + o] = fmaf(a2.x, xb[8], acd);
                }

                if (g == 0) {
                    *(float4*)&chunk[0]  = *(const float4*)&y[0];
                    *(float4*)&chunk[4]  = *(const float4*)&y[4];
                    *(float4*)&chunk[8]  = *(const float4*)&y[8];
                    *(float4*)&chunk[12] = *(const float4*)&y[12];
                    *(float2*)&chunk[16] = *(const float2*)&y[16];
                } else {
                    *(float2*)&chunk[18] = *(const float2*)&y[0];
                    *(float4*)&chunk[20] = *(const float4*)&y[2];
                    *(float4*)&chunk[24] = *(const float4*)&y[6];
                    *(float4*)&chunk[28] = *(const float4*)&y[10];
                    *(float4*)&chunk[32] = *(const float4*)&y[14];
                }
            }

            __syncthreads();  // all y written before async store reads smem
            if (t == 0) {
                asm volatile("fence.proxy.async.shared::cta;" ::: "memory");
                asm volatile(
                    "cp.async.bulk.global.shared::cta.bulk_group [%0], [%1], %2;"
                    :: "l"(og), "r"(smem_u32(buf)), "r"((uint32_t)BYTES_PER_TILE)
                    : "memory");
                asm volatile("cp.async.bulk.commit_group;" ::: "memory");
            }
            // no wait: store drains while we move on
        } else {
            // ---- partial tile (global last tile only): synchronous path ----
            if (t == 0) {
                asm volatile("cp.async.bulk.wait_group.read 0;" ::: "memory");
            }
            __syncthreads();
#pragma unroll
            for (int k = 0; k < (WORDS_PER_TILE / (TPB * 4)); k++) {
                int fi = (k * TPB + t) * 4;
                if (fi + 4 <= cnt) {
                    *(float4*)&buf[fi] = *(const float4*)&xg[fi];
                } else if (fi < cnt) {
                    for (int u = fi; u < cnt; u++) buf[u] = xg[u];
                }
            }
            __syncthreads();
            int lr0 = t * RPT;
            for (int lr = lr0; lr < lr0 + RPT && lr < rows_here; lr++) {
                float xp[9];
#pragma unroll
                for (int c = 0; c < 9; c++) xp[c] = buf[lr * 9 + c];
#pragma unroll
                for (int o = 0; o < 9; o++) {
                    float acc = c_aff[o * 12 + 9];
#pragma unroll
                    for (int c = 0; c < 9; c++)
                        acc = fmaf(c_aff[o * 12 + c], xp[c], acc);
                    buf[lr * 9 + o] = acc;
                }
            }
            __syncthreads();
#pragma unroll
            for (int k = 0; k < (WORDS_PER_TILE / (TPB * 4)); k++) {
                int fi = (k * TPB + t) * 4;
                if (fi + 4 <= cnt) {
                    *(float4*)&og[fi] = *(const float4*)&buf[fi];
                } else if (fi < cnt) {
                    for (int u = fi; u < cnt; u++) og[u] = buf[u];
                }
            }
        }
    }

    // drain the last async store before exit
    if (t == 0) {
        asm volatile("cp.async.bulk.wait_group 0;" ::: "memory");
    }
}

extern "C" void kernel_launch(void* const* d_in, const int* in_sizes, int n_in,
                              void* d_out, int out_size) {
    const float* x = (const float*)d_in[0];  // [N*9]
    const float* w = (const float*)d_in[1];  // [8*9]
    const float* b = (const float*)d_in[2];  // [8]
    float* out = (float*)d_out;              // [N*9]

    int nrows = in_sizes[0] / 9;

    compose_kernel<<<1, 96>>>(w, b);

    // Copy the composed affine map into __constant__ memory (D2D memcpy node;
    // graph-capturable, no allocation).
    void* g_aff_ptr = nullptr;
    cudaGetSymbolAddress(&g_aff_ptr, g_aff);
    cudaMemcpyToSymbolAsync(c_aff, g_aff_ptr, 9 * 12 * sizeof(float), 0,
                            cudaMemcpyDeviceToDevice);

    int ntiles = (nrows + ROWS_PER_TILE - 1) / ROWS_PER_TILE;
    int blocks = 148 * 6;
    if (blocks > ntiles) blocks = ntiles;
    affine_kernel<<<blocks, TPB>>>(x, out, nrows);
}